// round 6
// baseline (speedup 1.0000x reference)
#include <cuda_runtime.h>

// Warp1DOp: all-channel smem staging, one barrier.
// Block = one (n,h) row, 1024 threads.
//   Stage: all 32 channel rows (1280 px) -> padded smem rows via LDG.128/STS.128;
//          coords (dx, i0) computed once per pixel into smem float2.
//   Gather: warp wi handles channel wi; lane owns pixels {lane + 32k} (stride-1
//          -> coalesced STG.32, randomized smem banks for the two taps).
// Padded row: rowc[4+j] = img[j]; rowc[3] = rowc[1284] = 0 are the zero pads.
// Gather index i0 = floor(clip(w - disp, -1, W) + 1) + 3 in [3,1284], i1 = i0 + (dx>0).

#define N_ 4
#define C_ 32
#define H_ 384
#define W_ 1280
#define HW_ (H_ * W_)
#define CHW_ (C_ * HW_)
#define NH_ (N_ * H_)

#define RSTRIDE 1288                       // floats per padded smem row
#define ROWS_FLOATS (C_ * RSTRIDE)         // 41216 floats = 164864 B
#define SMEM_BYTES (ROWS_FLOATS * 4 + W_ * 8)   // + 1280 float2 coords

__global__ __launch_bounds__(1024, 1) void warp1d_kernel(
    const float* __restrict__ img,
    const float* __restrict__ disp,
    float* __restrict__ out)
{
    extern __shared__ float smem[];
    float*  rows   = smem;                                   // [C_][RSTRIDE]
    float2* coords = reinterpret_cast<float2*>(smem + ROWS_FLOATS);  // [W_]

    const int tid = threadIdx.x;
    const int nh  = blockIdx.x;              // n*H + h
    const size_t base = (size_t)(nh / H_) * CHW_ + (size_t)(nh % H_) * W_;

    // ---- zero pads (one thread per channel) ----
    if (tid < C_) {
        rows[tid * RSTRIDE + 3]    = 0.0f;
        rows[tid * RSTRIDE + 1284] = 0.0f;
    }

    // ---- stage all channel rows: 10 float4 per thread, fully coalesced ----
    const float4* __restrict__ isrc = reinterpret_cast<const float4*>(img + base);
#pragma unroll
    for (int it = 0; it < 10; ++it) {
        int idx4 = tid + it * 1024;          // over C_*W_/4 = 10240
        int c    = idx4 / (W_ / 4);
        int w4   = idx4 - c * (W_ / 4);
        // img row for channel c lives at base + c*HW_, contiguous W_ floats
        float4 v = isrc[(size_t)c * (HW_ / 4) + w4];
        *reinterpret_cast<float4*>(&rows[c * RSTRIDE + 4 + w4 * 4]) = v;
    }

    // ---- coords: computed once per pixel ----
    const float* __restrict__ drow = disp + (size_t)nh * W_;
#pragma unroll
    for (int px = tid; px < W_; px += 1024) {
        float d = __ldg(drow + px);
        float x = (float)px - d;
        x = fminf(fmaxf(x, -1.0f), (float)W_) + 1.0f;   // [0, W+1]
        float xf = floorf(x);
        float dx = x - xf;
        int   i0 = (int)xf + 3;                          // smem gather index
        coords[px] = make_float2(dx, __int_as_float(i0));
    }

    __syncthreads();

    // ---- gather: warp wi owns channel wi, lane owns px = lane + 32k ----
    const int c    = tid >> 5;
    const int lane = tid & 31;
    const float* __restrict__ rowc = rows + c * RSTRIDE;
    float* __restrict__ orow = out + base + (size_t)c * HW_;

#pragma unroll 8
    for (int k = 0; k < W_ / 32; ++k) {
        int px = lane + 32 * k;
        float2 cd = coords[px];              // conflict-free LDS.64
        float dx  = cd.x;
        int   i0  = __float_as_int(cd.y);
        int   i1  = i0 + (dx > 0.0f ? 1 : 0);
        float a = rowc[i0];
        float b = rowc[i1];
        orow[px] = (1.0f - dx) * a + dx * b; // coalesced STG.32
    }
}

extern "C" void kernel_launch(void* const* d_in, const int* in_sizes, int n_in,
                              void* d_out, int out_size)
{
    const float* img  = (const float*)d_in[0];
    const float* disp = (const float*)d_in[1];
    float* out = (float*)d_out;

    cudaFuncSetAttribute(warp1d_kernel,
                         cudaFuncAttributeMaxDynamicSharedMemorySize, SMEM_BYTES);
    warp1d_kernel<<<NH_, 1024, SMEM_BYTES>>>(img, disp, out);
}